// round 14
// baseline (speedup 1.0000x reference)
#include <cuda_runtime.h>
#include <cuda_fp16.h>
#include <cstdint>

// ---------------------------------------------------------------------------
// Problem constants
// ---------------------------------------------------------------------------
namespace {
constexpr int B_   = 4;
constexpr int S_   = 2048;
constexpr int H_   = 768;
constexpr int NH_  = 12;
constexpr int NKV_ = 2;
constexpr int HD_  = 64;
constexpr int GRP_ = NH_ / NKV_;      // 6
constexpr int TOK_ = B_ * S_;         // 8192
constexpr int QKVW_ = H_ + 2 * NKV_ * HD_;   // 1024 (q | k | v row width)
}

// ---------------------------------------------------------------------------
// Scratch (static device globals; no allocations allowed)
// ---------------------------------------------------------------------------
__device__ float    g_qkv [TOK_ * QKVW_];          // fp32 q|k|v rows, rope'd
__device__ uint32_t g_xh  [TOK_ * H_ / 2];         // half2-packed x
__device__ uint32_t g_wh  [QKVW_ * H_ / 2];        // wq rows 0..767 | wkv 768..1023
__device__ uint32_t g_woh [H_ * H_ / 2];
__device__ uint32_t g_atth[TOK_ * H_ / 2];         // half2-packed attention output

// ---------------------------------------------------------------------------
// helpers
// ---------------------------------------------------------------------------
__device__ __forceinline__ uint32_t pack_half2(float lo, float hi) {
    uint32_t r;
    asm("cvt.rn.f16x2.f32 %0, %1, %2;" : "=r"(r) : "f"(hi), "f"(lo));
    return r;
}

__device__ __forceinline__ float ex2(float x) {   // MUFU exp2
    float r;
    asm("ex2.approx.ftz.f32 %0, %1;" : "=f"(r) : "f"(x));
    return r;
}

__device__ __forceinline__ void mma_f16(float c[4], const uint32_t a[4],
                                        uint32_t b0, uint32_t b1) {
    asm volatile(
        "mma.sync.aligned.m16n8k16.row.col.f32.f16.f16.f32 "
        "{%0,%1,%2,%3}, {%4,%5,%6,%7}, {%8,%9}, {%0,%1,%2,%3};\n"
        : "+f"(c[0]), "+f"(c[1]), "+f"(c[2]), "+f"(c[3])
        : "r"(a[0]), "r"(a[1]), "r"(a[2]), "r"(a[3]), "r"(b0), "r"(b1));
}

__device__ __forceinline__ void cp_async16(void* smem_dst, const void* gmem_src) {
    uint32_t sa = (uint32_t)__cvta_generic_to_shared(smem_dst);
    asm volatile("cp.async.ca.shared.global [%0], [%1], 16;\n"
                 :: "r"(sa), "l"(gmem_src));
}
__device__ __forceinline__ void cp_commit() {
    asm volatile("cp.async.commit_group;\n");
}
template <int N>
__device__ __forceinline__ void cp_wait() {
    asm volatile("cp.async.wait_group %0;\n" :: "n"(N));
}

// ---------------------------------------------------------------------------
// One fused fp32 -> half2 convert for all four inputs.
// ---------------------------------------------------------------------------
namespace {
constexpr int X4_   = TOK_ * H_ / 4;
constexpr int WQ4_  = H_ * H_ / 4;
constexpr int WKV4_ = 2 * NKV_ * HD_ * H_ / 4;
constexpr int WO4_  = H_ * H_ / 4;
constexpr int ALL4_ = X4_ + WQ4_ + WKV4_ + WO4_;
}

__global__ void cvt_all(const float* __restrict__ x,  const float* __restrict__ wq,
                        const float* __restrict__ wkv, const float* __restrict__ wo,
                        uint32_t* __restrict__ xh, uint32_t* __restrict__ wh,
                        uint32_t* __restrict__ woh)
{
    const int i = blockIdx.x * 256 + threadIdx.x;
    if (i >= ALL4_) return;
    const float4* src;
    uint32_t* dst;
    int j = i;
    if (j < X4_)                    { src = (const float4*)x   + j; dst = xh  + j * 2; }
    else if ((j -= X4_)  < WQ4_)    { src = (const float4*)wq  + j; dst = wh  + j * 2; }
    else if ((j -= WQ4_) < WKV4_)   { src = (const float4*)wkv + j; dst = wh  + (WQ4_ + j) * 2; }
    else { j -= WKV4_;                src = (const float4*)wo  + j; dst = woh + j * 2; }
    float4 v = *src;
    dst[0] = pack_half2(v.x, v.y);
    dst[1] = pack_half2(v.z, v.w);
}

// ---------------------------------------------------------------------------
// fp16 GEMM: C[M,N](f32) = A[M,K](half) * B[N,K](half)^T.
// 128x128 tile, BK=32, 128 threads / 4 warps, warp tile 64x64,
// cp.async double-buffered, smem stride 20 words (conflict-free).
// ---------------------------------------------------------------------------
constexpr int GM_SMEM = 2 * 2 * 128 * 20 * 4;   // 81920 B

__global__ __launch_bounds__(128, 2) void gemm_fp16(
    const __half* __restrict__ A, const __half* __restrict__ B,
    float* __restrict__ C, int M, int N, int K)
{
    extern __shared__ uint32_t GS[];   // As[2][2560] | Bs[2][2560]

    const int tid  = threadIdx.x;
    const int lane = tid & 31;
    const int warp = tid >> 5;
    const int wm   = (warp >> 1) * 64;
    const int wn   = (warp & 1) * 64;
    const int bm   = blockIdx.y * 128;
    const int bn   = blockIdx.x * 128;
    const int qr   = lane >> 2;
    const int qc   = lane & 3;

    float acc[4][8][4];
#pragma unroll
    for (int mt = 0; mt < 4; mt++)
#pragma unroll
        for (int nt = 0; nt < 8; nt++)
#pragma unroll
            for (int i = 0; i < 4; i++) acc[mt][nt][i] = 0.0f;

    const __half* Abase = A + (size_t)bm * K;
    const __half* Bbase = B + (size_t)bn * K;

    auto stage = [&](int buf, int kb) {
        uint32_t* As = GS + buf * 2560;
        uint32_t* Bs = GS + 5120 + buf * 2560;
        const __half* Ab = Abase + kb * 32;
        const __half* Bb = Bbase + kb * 32;
#pragma unroll
        for (int u = 0; u < 4; u++) {
            const int id = tid + u * 128;      // 0..511
            const int r  = id >> 2;
            const int s  = id & 3;
            cp_async16(As + r * 20 + s * 4, Ab + (size_t)r * K + s * 8);
            cp_async16(Bs + r * 20 + s * 4, Bb + (size_t)r * K + s * 8);
        }
    };

    const int nkb = K / 32;
    stage(0, 0);
    cp_commit();

    for (int kb = 0; kb < nkb; kb++) {
        __syncthreads();
        if (kb + 1 < nkb) stage((kb + 1) & 1, kb + 1);
        cp_commit();
        cp_wait<1>();
        __syncthreads();

        const uint32_t* As = GS + (kb & 1) * 2560;
        const uint32_t* Bs = GS + 5120 + (kb & 1) * 2560;

#pragma unroll
        for (int kk = 0; kk < 2; kk++) {
            const int base = kk * 8 + qc;
            uint32_t af[4][4], bf[8][2];
#pragma unroll
            for (int mt = 0; mt < 4; mt++) {
                const int m = wm + mt * 16 + qr;
                af[mt][0] = As[m * 20 + base];
                af[mt][1] = As[(m + 8) * 20 + base];
                af[mt][2] = As[m * 20 + base + 4];
                af[mt][3] = As[(m + 8) * 20 + base + 4];
            }
#pragma unroll
            for (int nt = 0; nt < 8; nt++) {
                const int n = wn + nt * 8 + qr;
                bf[nt][0] = Bs[n * 20 + base];
                bf[nt][1] = Bs[n * 20 + base + 4];
            }
#pragma unroll
            for (int mt = 0; mt < 4; mt++)
#pragma unroll
                for (int nt = 0; nt < 8; nt++)
                    mma_f16(acc[mt][nt], af[mt], bf[nt][0], bf[nt][1]);
        }
    }

#pragma unroll
    for (int mt = 0; mt < 4; mt++) {
        const int m = bm + wm + mt * 16 + qr;
#pragma unroll
        for (int nt = 0; nt < 8; nt++) {
            const int n = bn + wn + nt * 8 + qc * 2;
            *(float2*)&C[(size_t)m * N + n] =
                make_float2(acc[mt][nt][0], acc[mt][nt][1]);
            *(float2*)&C[(size_t)(m + 8) * N + n] =
                make_float2(acc[mt][nt][2], acc[mt][nt][3]);
        }
    }
}

// ---------------------------------------------------------------------------
// RoPE in-place on Q cols [0,768) and K cols [768,896) of qkv rows
// ---------------------------------------------------------------------------
__global__ void rope_kernel(float* __restrict__ qkv)
{
    const int NQ = TOK_ * NH_  * 32;
    const int NK = TOK_ * NKV_ * 32;
    const int i = blockIdx.x * blockDim.x + threadIdx.x;
    if (i >= NQ + NK) return;

    float* base;
    int t, p;
    if (i < NQ) {
        t = i / (NH_ * 32);
        const int r = i % (NH_ * 32);
        const int h = r / 32;
        p = r & 31;
        base = qkv + (size_t)t * QKVW_ + h * HD_;
    } else {
        const int j = i - NQ;
        t = j / (NKV_ * 32);
        const int r = j % (NKV_ * 32);
        const int h = r / 32;
        p = r & 31;
        base = qkv + (size_t)t * QKVW_ + H_ + h * HD_;
    }
    const int s = t & (S_ - 1);
    const float inv = ex2(-(float)p * 0.41524101186092029f);
    const float ang = (float)s * inv;
    float sn, c;
    __sincosf(ang, &sn, &c);
    const float x0 = base[p], x1 = base[p + 32];
    base[p]      = x0 * c - x1 * sn;
    base[p + 32] = x1 * c + x0 * sn;
}

// ---------------------------------------------------------------------------
// Causal flash attention, fp16 m16n8k16 MMA.
// R14: 256 threads / 8 warps / 16 query rows per warp -> per-thread state
// halves (sf 32 + of 32 + qf 16 regs), fits 128 regs @ 2 blocks/SM
// (16 warps/SM). Same smem layouts as R13.
// ---------------------------------------------------------------------------
__global__ __launch_bounds__(256, 2) void flash_f16(
    const float* __restrict__ QKV, uint32_t* __restrict__ Oh)
{
    __shared__ uint32_t Ks[64 * 36];   // 9216 B
    __shared__ uint32_t Vs[64 * 36];   // 9216 B

    const int tid  = threadIdx.x;
    const int lane = tid & 31;
    const int warp = tid >> 5;         // 0..7
    const int qr   = lane >> 2;
    const int qc   = lane & 3;
    const int bh   = blockIdx.y;
    const int b    = bh / NH_;
    const int h    = bh % NH_;
    const int g    = h / GRP_;
    const int m0   = ((int)gridDim.x - 1 - (int)blockIdx.x) * 128;  // heavy first
    const int wrow = warp * 16;        // 0..112

    // ---- stage Q (scaled by log2e/8) as half2 d-pairs into Ks/Vs ----
    const float qs = 0.125f * 1.44269504088896341f;
#pragma unroll
    for (int u = 0; u < 8; u++) {
        const int i  = tid + u * 256;
        const int r  = i >> 4;
        const int d4 = (i & 15) * 4;
        const float* qp = QKV + (size_t)(b * S_ + m0 + r) * QKVW_ + h * HD_ + d4;
        float4 v = *(const float4*)qp;
        uint32_t* dst = (r < 64) ? &Ks[r * 36 + d4 / 2]
                                 : &Vs[(r - 64) * 36 + d4 / 2];
        dst[0] = pack_half2(v.x * qs, v.y * qs);
        dst[1] = pack_half2(v.z * qs, v.w * qs);
    }
    __syncthreads();

    // qf[kg] = A-frag for k-group kg (d = kg*16 .. kg*16+15)
    uint32_t qf[4][4];
    {
        const uint32_t* Qa = (wrow < 64) ? &Ks[wrow * 36]
                                         : &Vs[(wrow - 64) * 36];
#pragma unroll
        for (int kg = 0; kg < 4; kg++) {
            const int c = kg * 8 + qc;
            qf[kg][0] = Qa[qr * 36 + c];
            qf[kg][1] = Qa[(qr + 8) * 36 + c];
            qf[kg][2] = Qa[qr * 36 + c + 4];
            qf[kg][3] = Qa[(qr + 8) * 36 + c + 4];
        }
    }

    float of[8][4];
#pragma unroll
    for (int dt = 0; dt < 8; dt++)
#pragma unroll
        for (int i = 0; i < 4; i++) of[dt][i] = 0.0f;
    float m_run0 = -1e30f, m_run1 = -1e30f;
    float l_run0 = 0.0f,   l_run1 = 0.0f;

    const size_t kvbase = (size_t)(b * S_) * QKVW_ + H_ + g * HD_;
    const int ntiles = m0 / 64 + 2;

    for (int kt = 0; kt < ntiles; kt++) {
        const int k0 = kt * 64;
        __syncthreads();
        // K: word(key, dp) = half2(K[key][2dp], K[key][2dp+1])
#pragma unroll
        for (int u = 0; u < 4; u++) {
            const int i   = tid + u * 256;
            const int key = i >> 4;
            const int d4  = (i & 15) * 4;
            float4 k4 = *(const float4*)(QKV + kvbase +
                                         (size_t)(k0 + key) * QKVW_ + d4);
            Ks[key * 36 + d4 / 2]     = pack_half2(k4.x, k4.y);
            Ks[key * 36 + d4 / 2 + 1] = pack_half2(k4.z, k4.w);
        }
        // V: word(d, kp) = half2(V[2kp][d], V[2kp+1][d])  (d-major)
#pragma unroll
        for (int u = 0; u < 8; u++) {
            const int i  = tid + u * 256;
            const int d  = i & 63;
            const int kp = i >> 6;
            const float* vp = QKV + kvbase +
                              (size_t)(k0 + 2 * kp) * QKVW_ + 2 * HD_ + d;
            Vs[d * 36 + kp] = pack_half2(vp[0], vp[QKVW_]);
        }
        __syncthreads();

        if (k0 > m0 + wrow + 15) continue;   // warp fully above the diagonal

        // ---- S = Q K^T (16 x 64 per warp) ----
        float sf[8][4];
#pragma unroll
        for (int nt = 0; nt < 8; nt++)
#pragma unroll
            for (int i = 0; i < 4; i++) sf[nt][i] = 0.0f;
#pragma unroll
        for (int kg = 0; kg < 4; kg++) {
#pragma unroll
            for (int nt = 0; nt < 8; nt++) {
                uint32_t b0 = Ks[(nt * 8 + qr) * 36 + kg * 8 + qc];
                uint32_t b1 = Ks[(nt * 8 + qr) * 36 + kg * 8 + qc + 4];
                mma_f16(sf[nt], qf[kg], b0, b1);
            }
        }

        // ---- causal mask (diagonal region only) ----
        if (k0 + 63 > m0 + wrow) {
            const int r0 = m0 + wrow + qr;
#pragma unroll
            for (int nt = 0; nt < 8; nt++) {
                const int cL = k0 + nt * 8 + qc * 2;
                if (cL     > r0)     sf[nt][0] = -1e30f;
                if (cL + 1 > r0)     sf[nt][1] = -1e30f;
                if (cL     > r0 + 8) sf[nt][2] = -1e30f;
                if (cL + 1 > r0 + 8) sf[nt][3] = -1e30f;
            }
        }

        // ---- online softmax (MUFU ex2); P half2 bits packed into sf ----
        {
            float tm0 = -1e30f, tm1 = -1e30f;
#pragma unroll
            for (int nt = 0; nt < 8; nt++) {
                tm0 = fmaxf(tm0, fmaxf(sf[nt][0], sf[nt][1]));
                tm1 = fmaxf(tm1, fmaxf(sf[nt][2], sf[nt][3]));
            }
            tm0 = fmaxf(tm0, __shfl_xor_sync(0xffffffffu, tm0, 1));
            tm0 = fmaxf(tm0, __shfl_xor_sync(0xffffffffu, tm0, 2));
            tm1 = fmaxf(tm1, __shfl_xor_sync(0xffffffffu, tm1, 1));
            tm1 = fmaxf(tm1, __shfl_xor_sync(0xffffffffu, tm1, 2));

            const float mn0 = fmaxf(m_run0, tm0);
            const float mn1 = fmaxf(m_run1, tm1);
            const float cor0 = ex2(m_run0 - mn0);
            const float cor1 = ex2(m_run1 - mn1);
            m_run0 = mn0; m_run1 = mn1;

            float rs0 = 0.0f, rs1 = 0.0f;
#pragma unroll
            for (int nt = 0; nt < 8; nt++) {
                const float p0 = ex2(sf[nt][0] - mn0);
                const float p1 = ex2(sf[nt][1] - mn0);
                const float p2 = ex2(sf[nt][2] - mn1);
                const float p3 = ex2(sf[nt][3] - mn1);
                rs0 += p0 + p1;
                rs1 += p2 + p3;
                sf[nt][0] = __uint_as_float(pack_half2(p0, p1));
                sf[nt][1] = __uint_as_float(pack_half2(p2, p3));
            }
            rs0 += __shfl_xor_sync(0xffffffffu, rs0, 1);
            rs0 += __shfl_xor_sync(0xffffffffu, rs0, 2);
            rs1 += __shfl_xor_sync(0xffffffffu, rs1, 1);
            rs1 += __shfl_xor_sync(0xffffffffu, rs1, 2);
            l_run0 = l_run0 * cor0 + rs0;
            l_run1 = l_run1 * cor1 + rs1;
#pragma unroll
            for (int dt = 0; dt < 8; dt++) {
                of[dt][0] *= cor0; of[dt][1] *= cor0;
                of[dt][2] *= cor1; of[dt][3] *= cor1;
            }
        }

        // ---- O += P V  (A-frag = packed P bits from sf) ----
#pragma unroll
        for (int kg = 0; kg < 4; kg++) {
            uint32_t af[4];
            af[0] = __float_as_uint(sf[2 * kg][0]);
            af[1] = __float_as_uint(sf[2 * kg][1]);
            af[2] = __float_as_uint(sf[2 * kg + 1][0]);
            af[3] = __float_as_uint(sf[2 * kg + 1][1]);
#pragma unroll
            for (int dt = 0; dt < 8; dt++) {
                const int d = dt * 8 + qr;
                uint32_t v0 = Vs[d * 36 + kg * 8 + qc];
                uint32_t v1 = Vs[d * 36 + kg * 8 + qc + 4];
                mma_f16(of[dt], af, v0, v1);
            }
        }
    }

    // ---- epilogue: write packed half2 att ----
    {
        const float inv0 = 1.0f / l_run0;
        const float inv1 = 1.0f / l_run1;
        const int r0 = m0 + wrow + qr;
#pragma unroll
        for (int dt = 0; dt < 8; dt++) {
            const int col = h * HD_ + dt * 8 + qc * 2;
            Oh[((size_t)(b * S_ + r0) * H_ + col) >> 1] =
                pack_half2(of[dt][0] * inv0, of[dt][1] * inv0);
            Oh[((size_t)(b * S_ + r0 + 8) * H_ + col) >> 1] =
                pack_half2(of[dt][2] * inv1, of[dt][3] * inv1);
        }
    }
}

// ---------------------------------------------------------------------------
// Launch
// ---------------------------------------------------------------------------
extern "C" void kernel_launch(void* const* d_in, const int* in_sizes, int n_in,
                              void* d_out, int out_size)
{
    const float* x   = (const float*)d_in[0];
    const float* wq  = (const float*)d_in[1];
    const float* wkv = (const float*)d_in[2];
    const float* wo  = (const float*)d_in[3];
    float* out = (float*)d_out;

    float* qkv;
    uint32_t *xh, *wh, *woh, *atth;
    cudaGetSymbolAddress((void**)&qkv,  g_qkv);
    cudaGetSymbolAddress((void**)&xh,   g_xh);
    cudaGetSymbolAddress((void**)&wh,   g_wh);
    cudaGetSymbolAddress((void**)&woh,  g_woh);
    cudaGetSymbolAddress((void**)&atth, g_atth);

    cudaFuncSetAttribute(gemm_fp16,
                         cudaFuncAttributeMaxDynamicSharedMemorySize, GM_SMEM);

    cvt_all<<<(ALL4_ + 255) / 256, 256>>>(x, wq, wkv, wo, xh, wh, woh);

    gemm_fp16<<<dim3(QKVW_ / 128, TOK_ / 128), 128, GM_SMEM>>>(
        (const __half*)xh, (const __half*)wh, qkv, TOK_, QKVW_, H_);

    const int nrope = TOK_ * (NH_ + NKV_) * 32;
    rope_kernel<<<(nrope + 255) / 256, 256>>>(qkv);

    flash_f16<<<dim3(S_ / 128, B_ * NH_), 256>>>(qkv, atth);

    gemm_fp16<<<dim3(H_ / 128, TOK_ / 128), 128, GM_SMEM>>>(
        (const __half*)atth, (const __half*)woh, out, TOK_, H_, H_);
}

// round 15
// speedup vs baseline: 1.1152x; 1.1152x over previous
#include <cuda_runtime.h>
#include <cuda_fp16.h>
#include <cstdint>

// ---------------------------------------------------------------------------
// Problem constants
// ---------------------------------------------------------------------------
namespace {
constexpr int B_   = 4;
constexpr int S_   = 2048;
constexpr int H_   = 768;
constexpr int NH_  = 12;
constexpr int NKV_ = 2;
constexpr int HD_  = 64;
constexpr int GRP_ = NH_ / NKV_;      // 6
constexpr int TOK_ = B_ * S_;         // 8192
constexpr int QKVW_ = H_ + 2 * NKV_ * HD_;   // 1024
}

// ---------------------------------------------------------------------------
// Scratch (static device globals; no allocations allowed)
// ---------------------------------------------------------------------------
__device__ float    g_qkv [TOK_ * QKVW_];          // fp32 gemm1 output
__device__ uint32_t g_xh  [TOK_ * H_ / 2];         // half2-packed x
__device__ uint32_t g_wh  [QKVW_ * H_ / 2];        // [wq ; wkv] half
__device__ uint32_t g_woh [H_ * H_ / 2];
__device__ uint32_t g_atth[TOK_ * H_ / 2];         // half2-packed attention out
__device__ __half   g_qh  [TOK_ * H_];             // rope'd, pre-scaled Q half
__device__ __half   g_kh  [B_ * NKV_ * S_ * HD_];  // rope'd K half [bg][s][64]
__device__ uint32_t g_vt  [B_ * NKV_ * HD_ * S_ / 2]; // V key-pair half2 [bg][d][S/2]

// ---------------------------------------------------------------------------
// helpers
// ---------------------------------------------------------------------------
__device__ __forceinline__ uint32_t pack_half2(float lo, float hi) {
    uint32_t r;
    asm("cvt.rn.f16x2.f32 %0, %1, %2;" : "=r"(r) : "f"(hi), "f"(lo));
    return r;
}

__device__ __forceinline__ float ex2(float x) {
    float r;
    asm("ex2.approx.ftz.f32 %0, %1;" : "=f"(r) : "f"(x));
    return r;
}

__device__ __forceinline__ void mma_f16(float c[4], const uint32_t a[4],
                                        uint32_t b0, uint32_t b1) {
    asm volatile(
        "mma.sync.aligned.m16n8k16.row.col.f32.f16.f16.f32 "
        "{%0,%1,%2,%3}, {%4,%5,%6,%7}, {%8,%9}, {%0,%1,%2,%3};\n"
        : "+f"(c[0]), "+f"(c[1]), "+f"(c[2]), "+f"(c[3])
        : "r"(a[0]), "r"(a[1]), "r"(a[2]), "r"(a[3]), "r"(b0), "r"(b1));
}

__device__ __forceinline__ void cp_async16(void* smem_dst, const void* gmem_src) {
    uint32_t sa = (uint32_t)__cvta_generic_to_shared(smem_dst);
    asm volatile("cp.async.ca.shared.global [%0], [%1], 16;\n"
                 :: "r"(sa), "l"(gmem_src));
}
__device__ __forceinline__ void cp_commit() {
    asm volatile("cp.async.commit_group;\n");
}
template <int N>
__device__ __forceinline__ void cp_wait() {
    asm volatile("cp.async.wait_group %0;\n" :: "n"(N));
}

// ---------------------------------------------------------------------------
// One fused fp32 -> half2 convert for gemm inputs.
// ---------------------------------------------------------------------------
namespace {
constexpr int X4_   = TOK_ * H_ / 4;
constexpr int WQ4_  = H_ * H_ / 4;
constexpr int WKV4_ = 2 * NKV_ * HD_ * H_ / 4;
constexpr int WO4_  = H_ * H_ / 4;
constexpr int ALL4_ = X4_ + WQ4_ + WKV4_ + WO4_;
}

__global__ void cvt_all(const float* __restrict__ x,  const float* __restrict__ wq,
                        const float* __restrict__ wkv, const float* __restrict__ wo,
                        uint32_t* __restrict__ xh, uint32_t* __restrict__ wh,
                        uint32_t* __restrict__ woh)
{
    const int i = blockIdx.x * 256 + threadIdx.x;
    if (i >= ALL4_) return;
    const float4* src;
    uint32_t* dst;
    int j = i;
    if (j < X4_)                    { src = (const float4*)x   + j; dst = xh  + j * 2; }
    else if ((j -= X4_)  < WQ4_)    { src = (const float4*)wq  + j; dst = wh  + j * 2; }
    else if ((j -= WQ4_) < WKV4_)   { src = (const float4*)wkv + j; dst = wh  + (WQ4_ + j) * 2; }
    else { j -= WKV4_;                src = (const float4*)wo  + j; dst = woh + j * 2; }
    float4 v = *src;
    dst[0] = pack_half2(v.x, v.y);
    dst[1] = pack_half2(v.z, v.w);
}

// ---------------------------------------------------------------------------
// fp16 GEMM: C[M,N](f32) = A[M,K](half) * B[N,K](half)^T.  (unchanged R13)
// ---------------------------------------------------------------------------
constexpr int GM_SMEM = 2 * 2 * 128 * 20 * 4;   // 81920 B

__global__ __launch_bounds__(128, 2) void gemm_fp16(
    const __half* __restrict__ A, const __half* __restrict__ B,
    float* __restrict__ C, int M, int N, int K)
{
    extern __shared__ uint32_t GS[];

    const int tid  = threadIdx.x;
    const int lane = tid & 31;
    const int warp = tid >> 5;
    const int wm   = (warp >> 1) * 64;
    const int wn   = (warp & 1) * 64;
    const int bm   = blockIdx.y * 128;
    const int bn   = blockIdx.x * 128;
    const int qr   = lane >> 2;
    const int qc   = lane & 3;

    float acc[4][8][4];
#pragma unroll
    for (int mt = 0; mt < 4; mt++)
#pragma unroll
        for (int nt = 0; nt < 8; nt++)
#pragma unroll
            for (int i = 0; i < 4; i++) acc[mt][nt][i] = 0.0f;

    const __half* Abase = A + (size_t)bm * K;
    const __half* Bbase = B + (size_t)bn * K;

    auto stage = [&](int buf, int kb) {
        uint32_t* As = GS + buf * 2560;
        uint32_t* Bs = GS + 5120 + buf * 2560;
        const __half* Ab = Abase + kb * 32;
        const __half* Bb = Bbase + kb * 32;
#pragma unroll
        for (int u = 0; u < 4; u++) {
            const int id = tid + u * 128;
            const int r  = id >> 2;
            const int s  = id & 3;
            cp_async16(As + r * 20 + s * 4, Ab + (size_t)r * K + s * 8);
            cp_async16(Bs + r * 20 + s * 4, Bb + (size_t)r * K + s * 8);
        }
    };

    const int nkb = K / 32;
    stage(0, 0);
    cp_commit();

    for (int kb = 0; kb < nkb; kb++) {
        __syncthreads();
        if (kb + 1 < nkb) stage((kb + 1) & 1, kb + 1);
        cp_commit();
        cp_wait<1>();
        __syncthreads();

        const uint32_t* As = GS + (kb & 1) * 2560;
        const uint32_t* Bs = GS + 5120 + (kb & 1) * 2560;

#pragma unroll
        for (int kk = 0; kk < 2; kk++) {
            const int base = kk * 8 + qc;
            uint32_t af[4][4], bf[8][2];
#pragma unroll
            for (int mt = 0; mt < 4; mt++) {
                const int m = wm + mt * 16 + qr;
                af[mt][0] = As[m * 20 + base];
                af[mt][1] = As[(m + 8) * 20 + base];
                af[mt][2] = As[m * 20 + base + 4];
                af[mt][3] = As[(m + 8) * 20 + base + 4];
            }
#pragma unroll
            for (int nt = 0; nt < 8; nt++) {
                const int n = wn + nt * 8 + qr;
                bf[nt][0] = Bs[n * 20 + base];
                bf[nt][1] = Bs[n * 20 + base + 4];
            }
#pragma unroll
            for (int mt = 0; mt < 4; mt++)
#pragma unroll
                for (int nt = 0; nt < 8; nt++)
                    mma_f16(acc[mt][nt], af[mt], bf[nt][0], bf[nt][1]);
        }
    }

#pragma unroll
    for (int mt = 0; mt < 4; mt++) {
        const int m = bm + wm + mt * 16 + qr;
#pragma unroll
        for (int nt = 0; nt < 8; nt++) {
            const int n = bn + wn + nt * 8 + qc * 2;
            *(float2*)&C[(size_t)m * N + n] =
                make_float2(acc[mt][nt][0], acc[mt][nt][1]);
            *(float2*)&C[(size_t)(m + 8) * N + n] =
                make_float2(acc[mt][nt][2], acc[mt][nt][3]);
        }
    }
}

// ---------------------------------------------------------------------------
// RoPE + convert: fp32 qkv -> half Qh (pre-scaled by log2e/8) and half Kh.
// ---------------------------------------------------------------------------
__global__ void rope_cvt(const float* __restrict__ qkv,
                         __half* __restrict__ Qh, __half* __restrict__ Kh)
{
    const int NQ = TOK_ * NH_  * 32;
    const int NK = TOK_ * NKV_ * 32;
    const int i = blockIdx.x * blockDim.x + threadIdx.x;
    if (i >= NQ + NK) return;

    const float qs = 0.125f * 1.44269504088896341f;
    if (i < NQ) {
        const int t = i / (NH_ * 32);
        const int r = i % (NH_ * 32);
        const int h = r / 32;
        const int p = r & 31;
        const float* base = qkv + (size_t)t * QKVW_ + h * HD_;
        const int s = t & (S_ - 1);
        const float inv = ex2(-(float)p * 0.41524101186092029f);
        float sn, c;
        __sincosf((float)s * inv, &sn, &c);
        const float x0 = base[p], x1 = base[p + 32];
        __half* dst = Qh + (size_t)t * H_ + h * HD_;
        dst[p]      = __float2half((x0 * c - x1 * sn) * qs);
        dst[p + 32] = __float2half((x1 * c + x0 * sn) * qs);
    } else {
        const int j = i - NQ;
        const int t = j / (NKV_ * 32);
        const int r = j % (NKV_ * 32);
        const int g = r / 32;
        const int p = r & 31;
        const float* base = qkv + (size_t)t * QKVW_ + H_ + g * HD_;
        const int b = t >> 11;
        const int s = t & (S_ - 1);
        const float inv = ex2(-(float)p * 0.41524101186092029f);
        float sn, c;
        __sincosf((float)s * inv, &sn, &c);
        const float x0 = base[p], x1 = base[p + 32];
        __half* dst = Kh + ((size_t)(b * NKV_ + g) * S_ + s) * HD_;
        dst[p]      = __float2half(x0 * c - x1 * sn);
        dst[p + 32] = __float2half(x1 * c + x0 * sn);
    }
}

// ---------------------------------------------------------------------------
// V transpose + convert: fp32 V (cols 896+g*64 of qkv) ->
//   Vt[(bg*64 + d) * (S/2) + s/2] = half2(V[s][d], V[s+1][d])
// ---------------------------------------------------------------------------
__global__ void vtrans(const float* __restrict__ qkv, uint32_t* __restrict__ Vt)
{
    __shared__ float tile[64][65];
    const int tid = threadIdx.x;
    const int s0  = blockIdx.x * 64;
    const int bg  = blockIdx.y;
    const int b   = bg / NKV_;
    const int g   = bg % NKV_;

    const float* src = qkv + ((size_t)(b * S_ + s0)) * QKVW_
                     + H_ + NKV_ * HD_ + g * HD_;
#pragma unroll
    for (int u = 0; u < 4; u++) {
        const int idx4 = tid + u * 256;          // 0..1023
        const int t  = idx4 >> 4;
        const int d4 = (idx4 & 15) * 4;
        float4 v = *(const float4*)(src + (size_t)t * QKVW_ + d4);
        tile[t][d4] = v.x; tile[t][d4 + 1] = v.y;
        tile[t][d4 + 2] = v.z; tile[t][d4 + 3] = v.w;
    }
    __syncthreads();

#pragma unroll
    for (int u = 0; u < 8; u++) {
        const int idx = tid + u * 256;           // 0..2047
        const int d  = idx >> 5;
        const int kp = idx & 31;
        Vt[((size_t)bg * HD_ + d) * (S_ / 2) + (s0 >> 1) + kp] =
            pack_half2(tile[2 * kp][d], tile[2 * kp + 1][d]);
    }
}

// ---------------------------------------------------------------------------
// Causal flash attention, fp16 m16n8k16 MMA, 256 threads / 8 warps /
// 16 rows per warp.  R15: all operands pre-converted in gmem; staging is
// pure cp.async (4 chunks/thread/tile), double-buffered.
// Buffer layout per buf: Ks 64x36 words | Vs 64x36 words (stride 36,
// conflict-free b-frag loads).  Q staged once through buffer 0+1 space.
// ---------------------------------------------------------------------------
__global__ __launch_bounds__(256, 2) void flash_f16(
    const __half* __restrict__ Qh, const __half* __restrict__ Kh,
    const uint32_t* __restrict__ Vt, uint32_t* __restrict__ Oh)
{
    __shared__ uint32_t SB[2 * 4608];   // 36864 B

    const int tid  = threadIdx.x;
    const int lane = tid & 31;
    const int warp = tid >> 5;          // 0..7
    const int qr   = lane >> 2;
    const int qc   = lane & 3;
    const int bh   = blockIdx.y;
    const int b    = bh / NH_;
    const int h    = bh % NH_;
    const int g    = h / GRP_;
    const int m0   = ((int)gridDim.x - 1 - (int)blockIdx.x) * 128;  // heavy first
    const int wrow = warp * 16;

    // ---- stage Q (128 rows x 64 halves) via cp.async into SB rows ----
    {
        const __half* Qbase = Qh + (size_t)(b * S_ + m0) * H_ + h * HD_;
#pragma unroll
        for (int u = 0; u < 4; u++) {
            const int idx = tid + u * 256;   // 0..1023
            const int r   = idx >> 3;
            const int seg = idx & 7;
            cp_async16(SB + r * 36 + seg * 4, Qbase + (size_t)r * H_ + seg * 8);
        }
        cp_commit();
        cp_wait<0>();
        __syncthreads();
    }

    // qf[kg] = A-frag for k-group kg (d = kg*16 .. kg*16+15)
    uint32_t qf[4][4];
    {
        const uint32_t* Qa = SB + wrow * 36;
#pragma unroll
        for (int kg = 0; kg < 4; kg++) {
            const int c = kg * 8 + qc;
            qf[kg][0] = Qa[qr * 36 + c];
            qf[kg][1] = Qa[(qr + 8) * 36 + c];
            qf[kg][2] = Qa[qr * 36 + c + 4];
            qf[kg][3] = Qa[(qr + 8) * 36 + c + 4];
        }
    }
    __syncthreads();   // Q region free for K/V staging

    float of[8][4];
#pragma unroll
    for (int dt = 0; dt < 8; dt++)
#pragma unroll
        for (int i = 0; i < 4; i++) of[dt][i] = 0.0f;
    float m_run0 = -1e30f, m_run1 = -1e30f;
    float l_run0 = 0.0f,   l_run1 = 0.0f;

    const size_t kbase = (size_t)((b * NKV_ + g) * S_) * HD_;       // Kh halves
    const size_t vbase = (size_t)((b * NKV_ + g) * HD_) * (S_ / 2); // Vt words
    const int ntiles = m0 / 64 + 2;

    auto stage = [&](int kt, int bufi) {
        uint32_t* Kb = SB + bufi * 4608;
        uint32_t* Vb = Kb + 2304;
        const __half*   Ksrc = Kh + kbase + (size_t)(kt * 64) * HD_;
        const uint32_t* Vsrc = Vt + vbase + kt * 32;
#pragma unroll
        for (int u = 0; u < 2; u++) {
            const int idx = tid + u * 256;   // 0..511
            const int r   = idx >> 3;
            const int seg = idx & 7;
            cp_async16(Kb + r * 36 + seg * 4, Ksrc + (size_t)r * HD_ + seg * 8);
            cp_async16(Vb + r * 36 + seg * 4, Vsrc + (size_t)r * (S_ / 2) + seg * 4);
        }
    };

    stage(0, 0);
    cp_commit();

    for (int kt = 0; kt < ntiles; kt++) {
        const int buf = kt & 1;
        const int k0  = kt * 64;
        __syncthreads();                    // all compute on buf^1 done
        if (kt + 1 < ntiles) stage(kt + 1, buf ^ 1);
        cp_commit();
        cp_wait<1>();                       // tile kt resident
        __syncthreads();

        if (k0 > m0 + wrow + 15) continue;  // warp fully above the diagonal

        const uint32_t* Ks = SB + buf * 4608;
        const uint32_t* Vs = Ks + 2304;

        // ---- S = Q K^T (16 x 64 per warp) ----
        float sf[8][4];
#pragma unroll
        for (int nt = 0; nt < 8; nt++)
#pragma unroll
            for (int i = 0; i < 4; i++) sf[nt][i] = 0.0f;
#pragma unroll
        for (int kg = 0; kg < 4; kg++) {
#pragma unroll
            for (int nt = 0; nt < 8; nt++) {
                uint32_t b0 = Ks[(nt * 8 + qr) * 36 + kg * 8 + qc];
                uint32_t b1 = Ks[(nt * 8 + qr) * 36 + kg * 8 + qc + 4];
                mma_f16(sf[nt], qf[kg], b0, b1);
            }
        }

        // ---- causal mask (diagonal region only) ----
        if (k0 + 63 > m0 + wrow) {
            const int r0 = m0 + wrow + qr;
#pragma unroll
            for (int nt = 0; nt < 8; nt++) {
                const int cL = k0 + nt * 8 + qc * 2;
                if (cL     > r0)     sf[nt][0] = -1e30f;
                if (cL + 1 > r0)     sf[nt][1] = -1e30f;
                if (cL     > r0 + 8) sf[nt][2] = -1e30f;
                if (cL + 1 > r0 + 8) sf[nt][3] = -1e30f;
            }
        }

        // ---- online softmax (MUFU ex2); P half2 bits packed into sf ----
        {
            float tm0 = -1e30f, tm1 = -1e30f;
#pragma unroll
            for (int nt = 0; nt < 8; nt++) {
                tm0 = fmaxf(tm0, fmaxf(sf[nt][0], sf[nt][1]));
                tm1 = fmaxf(tm1, fmaxf(sf[nt][2], sf[nt][3]));
            }
            tm0 = fmaxf(tm0, __shfl_xor_sync(0xffffffffu, tm0, 1));
            tm0 = fmaxf(tm0, __shfl_xor_sync(0xffffffffu, tm0, 2));
            tm1 = fmaxf(tm1, __shfl_xor_sync(0xffffffffu, tm1, 1));
            tm1 = fmaxf(tm1, __shfl_xor_sync(0xffffffffu, tm1, 2));

            const float mn0 = fmaxf(m_run0, tm0);
            const float mn1 = fmaxf(m_run1, tm1);
            const float cor0 = ex2(m_run0 - mn0);
            const float cor1 = ex2(m_run1 - mn1);
            m_run0 = mn0; m_run1 = mn1;

            float rs0 = 0.0f, rs1 = 0.0f;
#pragma unroll
            for (int nt = 0; nt < 8; nt++) {
                const float p0 = ex2(sf[nt][0] - mn0);
                const float p1 = ex2(sf[nt][1] - mn0);
                const float p2 = ex2(sf[nt][2] - mn1);
                const float p3 = ex2(sf[nt][3] - mn1);
                rs0 += p0 + p1;
                rs1 += p2 + p3;
                sf[nt][0] = __uint_as_float(pack_half2(p0, p1));
                sf[nt][1] = __uint_as_float(pack_half2(p2, p3));
            }
            rs0 += __shfl_xor_sync(0xffffffffu, rs0, 1);
            rs0 += __shfl_xor_sync(0xffffffffu, rs0, 2);
            rs1 += __shfl_xor_sync(0xffffffffu, rs1, 1);
            rs1 += __shfl_xor_sync(0xffffffffu, rs1, 2);
            l_run0 = l_run0 * cor0 + rs0;
            l_run1 = l_run1 * cor1 + rs1;
#pragma unroll
            for (int dt = 0; dt < 8; dt++) {
                of[dt][0] *= cor0; of[dt][1] *= cor0;
                of[dt][2] *= cor1; of[dt][3] *= cor1;
            }
        }

        // ---- O += P V  (A-frag = packed P bits from sf) ----
#pragma unroll
        for (int kg = 0; kg < 4; kg++) {
            uint32_t af[4];
            af[0] = __float_as_uint(sf[2 * kg][0]);
            af[1] = __float_as_uint(sf[2 * kg][1]);
            af[2] = __float_as_uint(sf[2 * kg + 1][0]);
            af[3] = __float_as_uint(sf[2 * kg + 1][1]);
#pragma unroll
            for (int dt = 0; dt < 8; dt++) {
                const int d = dt * 8 + qr;
                uint32_t v0 = Vs[d * 36 + kg * 8 + qc];
                uint32_t v1 = Vs[d * 36 + kg * 8 + qc + 4];
                mma_f16(of[dt], af, v0, v1);
            }
        }
    }

    // ---- epilogue: write packed half2 att ----
    {
        const float inv0 = 1.0f / l_run0;
        const float inv1 = 1.0f / l_run1;
        const int r0 = m0 + wrow + qr;
#pragma unroll
        for (int dt = 0; dt < 8; dt++) {
            const int col = h * HD_ + dt * 8 + qc * 2;
            Oh[((size_t)(b * S_ + r0) * H_ + col) >> 1] =
                pack_half2(of[dt][0] * inv0, of[dt][1] * inv0);
            Oh[((size_t)(b * S_ + r0 + 8) * H_ + col) >> 1] =
                pack_half2(of[dt][2] * inv1, of[dt][3] * inv1);
        }
    }
}

// ---------------------------------------------------------------------------
// Launch
// ---------------------------------------------------------------------------
extern "C" void kernel_launch(void* const* d_in, const int* in_sizes, int n_in,
                              void* d_out, int out_size)
{
    const float* x   = (const float*)d_in[0];
    const float* wq  = (const float*)d_in[1];
    const float* wkv = (const float*)d_in[2];
    const float* wo  = (const float*)d_in[3];
    float* out = (float*)d_out;

    float* qkv;
    uint32_t *xh, *wh, *woh, *atth, *vt;
    __half *qh, *kh;
    cudaGetSymbolAddress((void**)&qkv,  g_qkv);
    cudaGetSymbolAddress((void**)&xh,   g_xh);
    cudaGetSymbolAddress((void**)&wh,   g_wh);
    cudaGetSymbolAddress((void**)&woh,  g_woh);
    cudaGetSymbolAddress((void**)&atth, g_atth);
    cudaGetSymbolAddress((void**)&qh,   g_qh);
    cudaGetSymbolAddress((void**)&kh,   g_kh);
    cudaGetSymbolAddress((void**)&vt,   g_vt);

    cudaFuncSetAttribute(gemm_fp16,
                         cudaFuncAttributeMaxDynamicSharedMemorySize, GM_SMEM);

    cvt_all<<<(ALL4_ + 255) / 256, 256>>>(x, wq, wkv, wo, xh, wh, woh);

    gemm_fp16<<<dim3(QKVW_ / 128, TOK_ / 128), 128, GM_SMEM>>>(
        (const __half*)xh, (const __half*)wh, qkv, TOK_, QKVW_, H_);

    const int nrope = TOK_ * (NH_ + NKV_) * 32;
    rope_cvt<<<(nrope + 255) / 256, 256>>>(qkv, qh, kh);
    vtrans<<<dim3(S_ / 64, B_ * NKV_), 256>>>(qkv, vt);

    flash_f16<<<dim3(S_ / 128, B_ * NH_), 256>>>(qh, kh, vt, atth);

    gemm_fp16<<<dim3(H_ / 128, TOK_ / 128), 128, GM_SMEM>>>(
        (const __half*)atth, (const __half*)woh, out, TOK_, H_, H_);
}